// round 8
// baseline (speedup 1.0000x reference)
#include <cuda_runtime.h>
#include <cuda_bf16.h>

#define DIM 512
#define NHEAD 16
#define HDIM 32
#define NB 1024
#define NTOK 49
#define MROWS (NB * NTOK)   // 50176
#define QSCALE 0.17677669529663687f  // 32^-0.5

// ---------------- scratch (__device__ globals; no allocs allowed) ----------
__device__ float g_Q[(size_t)MROWS * DIM];
__device__ float g_K[(size_t)MROWS * DIM];
__device__ float g_V[(size_t)MROWS * DIM];
__device__ float g_G[(size_t)MROWS * DIM];
__device__ __nv_bfloat16 g_Xh[3][(size_t)MROWS * DIM];   // x, x2, x3 hi
__device__ __nv_bfloat16 g_Xl[3][(size_t)MROWS * DIM];   // x, x2, x3 lo
__device__ __nv_bfloat16 g_Oh[(size_t)MROWS * DIM];
__device__ __nv_bfloat16 g_Ol[(size_t)MROWS * DIM];
__device__ __nv_bfloat16 g_Wh[5][DIM * DIM];
__device__ __nv_bfloat16 g_Wl[5][DIM * DIM];

// ---------------- helpers --------------------------------------------------
__device__ __forceinline__ unsigned smem_u32(const void* p) {
    unsigned a;
    asm("{ .reg .u64 t; cvta.to.shared.u64 t, %1; cvt.u32.u64 %0, t; }" : "=r"(a) : "l"(p));
    return a;
}
__device__ __forceinline__ unsigned pack_bf16(__nv_bfloat16 a, __nv_bfloat16 b) {
    return (unsigned)__bfloat16_as_ushort(a) | ((unsigned)__bfloat16_as_ushort(b) << 16);
}
__device__ __forceinline__ void ldsm4(unsigned* r, unsigned addr) {
    asm volatile("ldmatrix.sync.aligned.m8n8.x4.shared.b16 {%0,%1,%2,%3}, [%4];"
        : "=r"(r[0]), "=r"(r[1]), "=r"(r[2]), "=r"(r[3]) : "r"(addr));
}
__device__ __forceinline__ void mma16816(float* d, const unsigned* a, unsigned b0, unsigned b1) {
    asm volatile("mma.sync.aligned.m16n8k16.row.col.f32.bf16.bf16.f32 "
        "{%0,%1,%2,%3}, {%4,%5,%6,%7}, {%8,%9}, {%0,%1,%2,%3};"
        : "+f"(d[0]), "+f"(d[1]), "+f"(d[2]), "+f"(d[3])
        : "r"(a[0]), "r"(a[1]), "r"(a[2]), "r"(a[3]), "r"(b0), "r"(b1));
}
__device__ __forceinline__ void cpa16(unsigned saddr, const void* g) {
    asm volatile("cp.async.cg.shared.global [%0], [%1], 16;" :: "r"(saddr), "l"(g));
}
#define CP_COMMIT() asm volatile("cp.async.commit_group;" ::: "memory")
#define CP_WAIT0()  asm volatile("cp.async.wait_group 0;" ::: "memory")
#define CP_WAIT1()  asm volatile("cp.async.wait_group 1;" ::: "memory")

// ---------------------------------------------------------------------------
// Input split: fp32 -> hi/lo bf16 (elementwise, float4-vectorized)
// ---------------------------------------------------------------------------
__global__ void __launch_bounds__(256)
fsplit(const float* __restrict__ X, __nv_bfloat16* __restrict__ Xh,
       __nv_bfloat16* __restrict__ Xl, int n4) {
    int i = blockIdx.x * 256 + threadIdx.x;
    if (i >= n4) return;
    float4 v = ((const float4*)X)[i];
    __nv_bfloat16 h0 = __float2bfloat16(v.x), h1 = __float2bfloat16(v.y);
    __nv_bfloat16 h2 = __float2bfloat16(v.z), h3 = __float2bfloat16(v.w);
    __nv_bfloat16 l0 = __float2bfloat16(v.x - __bfloat162float(h0));
    __nv_bfloat16 l1 = __float2bfloat16(v.y - __bfloat162float(h1));
    __nv_bfloat16 l2 = __float2bfloat16(v.z - __bfloat162float(h2));
    __nv_bfloat16 l3 = __float2bfloat16(v.w - __bfloat162float(h3));
    uint2 ph = { pack_bf16(h0, h1), pack_bf16(h2, h3) };
    uint2 pl = { pack_bf16(l0, l1), pack_bf16(l2, l3) };
    ((uint2*)Xh)[i] = ph;
    ((uint2*)Xl)[i] = pl;
}

// ---------------------------------------------------------------------------
// Weight transpose + hi/lo split: T[n*512+k] = split(W[k*ldb + n])
// ---------------------------------------------------------------------------
__global__ void tsplit(const float* __restrict__ W, int ldb,
                       __nv_bfloat16* __restrict__ Th, __nv_bfloat16* __restrict__ Tl) {
    __shared__ float t[32][33];
    int k0 = blockIdx.x * 32, n0 = blockIdx.y * 32;
    int tx = threadIdx.x, ty = threadIdx.y;
#pragma unroll
    for (int j = 0; j < 32; j += 8)
        t[ty + j][tx] = W[(size_t)(k0 + ty + j) * ldb + n0 + tx];
    __syncthreads();
#pragma unroll
    for (int j = 0; j < 32; j += 8) {
        float v = t[tx][ty + j];
        __nv_bfloat16 h = __float2bfloat16(v);
        __nv_bfloat16 l = __float2bfloat16(v - __bfloat162float(h));
        size_t o = (size_t)(n0 + ty + j) * DIM + k0 + tx;
        Th[o] = h; Tl[o] = l;
    }
}

// ---------------------------------------------------------------------------
// Warp-MMA bf16 GEMM (3-pass hi/lo split -> fp32-grade accuracy).
//   C[M, 512] = (Ah+Al)[M, 512] @ (Bh+Bl)^T + bias   (al*bl dropped)
//   All operands pre-split bf16, K-major. CTA tile 128x128, 8 warps.
//   Software pipeline: stage = K32 half-chunk; the two halves of each 128B
//   smem row double-buffer each other (fill half h while MMA reads half 1-h).
// ---------------------------------------------------------------------------
#define OFF_AH 0
#define OFF_AL 16384
#define OFF_BH 32768
#define OFF_BL 49152
#define GEMM_SMEM 65536

__global__ void __launch_bounds__(256, 2)
gemm_tc(const __nv_bfloat16* __restrict__ Ah, const __nv_bfloat16* __restrict__ Al,
        const __nv_bfloat16* __restrict__ Bh, const __nv_bfloat16* __restrict__ Bl,
        const float* __restrict__ bias0, const float* __restrict__ bias1,
        float* __restrict__ C0, float* __restrict__ C1, int nsplit) {
    extern __shared__ char smem[];
    const unsigned sb = smem_u32(smem);
    const int tid = threadIdx.x, wid = tid >> 5, lane = tid & 31;
    const int n0 = blockIdx.x * 128, m0 = blockIdx.y * 128;

    const float* bias = (n0 < nsplit) ? bias0 : bias1;
    float* C = (n0 < nsplit) ? C0 : C1;
    const int nc0 = (n0 < nsplit) ? n0 : n0 - nsplit;

    const int wm = (wid >> 2) * 64;     // warp M offset (0 or 64)
    const int wn = (wid & 3) * 32;      // warp N offset (0,32,64,96)

    // ldmatrix per-lane geometry
    const int grp = lane >> 3, lr = lane & 7;
    const int rA = wm + lr + ((grp & 1) << 3);
    const int rB = wn + lr + ((grp & 1) << 3);
    const int cadd = (grp >> 1) & 1;
    const int amod = rA & 7;
    const int bmod = rB & 7;

    // fill lane geometry: g in [0,512) -> row (0..127), j (0..3)
    const int frow = tid >> 1;                 // g>>2 for g=tid*2.. use 2 iters
    float acc[4][4][4];
#pragma unroll
    for (int t = 0; t < 4; t++)
#pragma unroll
        for (int u = 0; u < 4; u++)
#pragma unroll
            for (int i = 0; i < 4; i++) acc[t][u][i] = 0.f;

    // ---- fill(cc): pure cp.async of K32 half-chunk into half (cc&1) ----
    auto fill = [&](int cc) {
#pragma unroll
        for (int it = 0; it < 2; ++it) {
            int g = tid + it * 256;            // 0..511
            int row = g >> 2, j = g & 3;
            unsigned sw = (unsigned)(row * 128) + (((unsigned)(((cc & 1) * 4 + j) ^ (row & 7))) << 4);
            size_t srcA = (size_t)(m0 + row) * DIM + cc * 32 + j * 8;
            size_t srcB = (size_t)(n0 + row) * DIM + cc * 32 + j * 8;
            cpa16(sb + OFF_AH + sw, Ah + srcA);
            cpa16(sb + OFF_AL + sw, Al + srcA);
            cpa16(sb + OFF_BH + sw, Bh + srcB);
            cpa16(sb + OFF_BL + sw, Bl + srcB);
        }
    };

    fill(0);
    CP_COMMIT();

    for (int cc = 0; cc < 16; ++cc) {
        if (cc < 15) { fill(cc + 1); CP_COMMIT(); CP_WAIT1(); }
        else         { CP_WAIT0(); }
        __syncthreads();

        // ---- MMA on half (cc&1): 2 ksteps ----
#pragma unroll
        for (int ks = 0; ks < 2; ++ks) {
            const int chk = (cc & 1) * 4 + ks * 2 + cadd;
            const unsigned aoff = (unsigned)(rA * 128) + (((unsigned)(chk ^ amod)) << 4);
            const unsigned boff = (unsigned)(rB * 128) + (((unsigned)(chk ^ bmod)) << 4);
            unsigned af[4][4], bh0[4], bh1[4], bl0[4], bl1[4];
            ldsm4(bh0, sb + OFF_BH + boff);
            ldsm4(bh1, sb + OFF_BH + boff + 16 * 128);
            ldsm4(bl0, sb + OFF_BL + boff);
            ldsm4(bl1, sb + OFF_BL + boff + 16 * 128);
#pragma unroll
            for (int t = 0; t < 4; ++t)
                ldsm4(af[t], sb + OFF_AH + aoff + t * 16 * 128);
#pragma unroll
            for (int t = 0; t < 4; ++t) {
                mma16816(acc[t][0], af[t], bh0[0], bh0[2]);
                mma16816(acc[t][1], af[t], bh0[1], bh0[3]);
                mma16816(acc[t][2], af[t], bh1[0], bh1[2]);
                mma16816(acc[t][3], af[t], bh1[1], bh1[3]);
            }
#pragma unroll
            for (int t = 0; t < 4; ++t) {
                mma16816(acc[t][0], af[t], bl0[0], bl0[2]);
                mma16816(acc[t][1], af[t], bl0[1], bl0[3]);
                mma16816(acc[t][2], af[t], bl1[0], bl1[2]);
                mma16816(acc[t][3], af[t], bl1[1], bl1[3]);
            }
#pragma unroll
            for (int t = 0; t < 4; ++t)
                ldsm4(af[t], sb + OFF_AL + aoff + t * 16 * 128);
#pragma unroll
            for (int t = 0; t < 4; ++t) {
                mma16816(acc[t][0], af[t], bh0[0], bh0[2]);
                mma16816(acc[t][1], af[t], bh0[1], bh0[3]);
                mma16816(acc[t][2], af[t], bh1[0], bh1[2]);
                mma16816(acc[t][3], af[t], bh1[1], bh1[3]);
            }
        }
        __syncthreads();
    }
    (void)frow;

    // ---- epilogue: direct stores with bias ----
#pragma unroll
    for (int u = 0; u < 4; ++u) {
        const int col = nc0 + wn + u * 8 + (lane & 3) * 2;
        const float bx = bias[col], by = bias[col + 1];
#pragma unroll
        for (int t = 0; t < 4; ++t) {
            const int row = m0 + wm + t * 16 + (lane >> 2);
            float2 o0 = { acc[t][u][0] + bx, acc[t][u][1] + by };
            float2 o1 = { acc[t][u][2] + bx, acc[t][u][3] + by };
            *(float2*)(C + (size_t)row * DIM + col) = o0;
            *(float2*)(C + (size_t)(row + 8) * DIM + col) = o1;
        }
    }
}

// ---------------------------------------------------------------------------
// Fused attention per (b, h); output written pre-split as hi/lo bf16.
// ---------------------------------------------------------------------------
__global__ __launch_bounds__(256)
void attn_kernel(const float* __restrict__ Q1, const float* __restrict__ G,
                 const float* __restrict__ Km, const float* __restrict__ Vm,
                 const float* __restrict__ a_ptr,
                 __nv_bfloat16* __restrict__ Oh, __nv_bfloat16* __restrict__ Ol) {
    __shared__ float qs[NTOK][HDIM + 1];
    __shared__ float ks[NTOK][HDIM + 1];
    __shared__ float vs[NTOK][HDIM + 1];
    __shared__ float S[NTOK][NTOK + 1];

    const int bh = blockIdx.x;
    const int b = bh >> 4;
    const int h = bh & 15;
    const int tid = threadIdx.x;
    const float a = *a_ptr;

    const size_t base = (size_t)b * NTOK * DIM + h * HDIM;

    for (int i = tid; i < NTOK * HDIM; i += 256) {
        int n = i >> 5, d = i & 31;
        size_t idx = base + (size_t)n * DIM + d;
        qs[n][d] = Q1[idx] * QSCALE * G[idx];
        ks[n][d] = Km[idx];
        vs[n][d] = Vm[idx];
    }
    __syncthreads();

    for (int i = tid; i < NTOK * NTOK; i += 256) {
        int n = i / NTOK, m = i - n * NTOK;
        float s = 0.f;
#pragma unroll
        for (int d = 0; d < HDIM; d++) s = fmaf(qs[n][d], ks[m][d], s);
        S[n][m] = s;
    }
    __syncthreads();

    const int warp = tid >> 5, lane = tid & 31;
    for (int n = warp; n < NTOK; n += 8) {
        float v1 = S[n][lane];
        float v2 = (lane + 32 < NTOK) ? S[n][lane + 32] : -1e30f;
        float mx = fmaxf(v1, v2);
#pragma unroll
        for (int off = 16; off; off >>= 1)
            mx = fmaxf(mx, __shfl_xor_sync(0xffffffffu, mx, off));
        float e1 = __expf(v1 - mx);
        float e2 = (lane + 32 < NTOK) ? __expf(v2 - mx) : 0.f;
        float sum = e1 + e2;
#pragma unroll
        for (int off = 16; off; off >>= 1)
            sum += __shfl_xor_sync(0xffffffffu, sum, off);
        float inv = 1.f / sum;
        S[n][lane] = e1 * inv;
        if (lane + 32 < NTOK) S[n][lane + 32] = e2 * inv;
    }
    __syncthreads();

    for (int i = tid; i < NTOK * HDIM; i += 256) {
        int n = i >> 5, d = i & 31;
        float o = vs[n][d] * a;
#pragma unroll
        for (int m = 0; m < NTOK; m++) o = fmaf(S[n][m], vs[m][d], o);
        size_t idx = base + (size_t)n * DIM + d;
        __nv_bfloat16 hh = __float2bfloat16(o);
        Oh[idx] = hh;
        Ol[idx] = __float2bfloat16(o - __bfloat162float(hh));
    }
}

// ---------------------------------------------------------------------------
extern "C" void kernel_launch(void* const* d_in, const int* in_sizes, int n_in,
                              void* d_out, int out_size) {
    const float* x     = (const float*)d_in[0];
    const float* x2    = (const float*)d_in[1];
    const float* x3    = (const float*)d_in[2];
    const float* Wqkv  = (const float*)d_in[3];
    const float* bqkv  = (const float*)d_in[4];
    const float* Wqkv2 = (const float*)d_in[5];
    const float* bqkv2 = (const float*)d_in[6];
    const float* Wgw   = (const float*)d_in[7];
    const float* bgw   = (const float*)d_in[8];
    const float* Wproj = (const float*)d_in[9];
    const float* bproj = (const float*)d_in[10];
    const float* a     = (const float*)d_in[11];
    float* out = (float*)d_out;

    float *Q, *K, *V, *G;
    cudaGetSymbolAddress((void**)&Q, g_Q);
    cudaGetSymbolAddress((void**)&K, g_K);
    cudaGetSymbolAddress((void**)&V, g_V);
    cudaGetSymbolAddress((void**)&G, g_G);
    __nv_bfloat16 *Xh, *Xl, *Oh, *Ol, *Wh, *Wl;
    cudaGetSymbolAddress((void**)&Xh, g_Xh);
    cudaGetSymbolAddress((void**)&Xl, g_Xl);
    cudaGetSymbolAddress((void**)&Oh, g_Oh);
    cudaGetSymbolAddress((void**)&Ol, g_Ol);
    cudaGetSymbolAddress((void**)&Wh, g_Wh);
    cudaGetSymbolAddress((void**)&Wl, g_Wl);

    const size_t PL = (size_t)MROWS * DIM;   // plane size
    cudaFuncSetAttribute(gemm_tc, cudaFuncAttributeMaxDynamicSharedMemorySize, GEMM_SMEM);

    // Input splits (x -> plane 0, x2 -> plane 1, x3 -> plane 2)
    const int n4 = (int)(PL / 4);
    fsplit<<<(n4 + 255) / 256, 256>>>(x,  Xh + 0 * PL, Xl + 0 * PL, n4);
    fsplit<<<(n4 + 255) / 256, 256>>>(x2, Xh + 1 * PL, Xl + 1 * PL, n4);
    fsplit<<<(n4 + 255) / 256, 256>>>(x3, Xh + 2 * PL, Xl + 2 * PL, n4);

    dim3 tsG(16, 16), tsB(32, 8);
    // weight slots: 0:K (Wqkv cols [512,1024)); 1:Q (Wqkv2 [0,512));
    // 2:V (Wqkv2 [1024,1536)) - slots 1,2 contiguous for fused QV; 3:gate; 4:proj
    tsplit<<<tsG, tsB>>>(Wqkv  + DIM,     3 * DIM, Wh + 0 * DIM * DIM, Wl + 0 * DIM * DIM);
    tsplit<<<tsG, tsB>>>(Wqkv2,           3 * DIM, Wh + 1 * DIM * DIM, Wl + 1 * DIM * DIM);
    tsplit<<<tsG, tsB>>>(Wqkv2 + 2 * DIM, 3 * DIM, Wh + 2 * DIM * DIM, Wl + 2 * DIM * DIM);
    tsplit<<<tsG, tsB>>>(Wgw,             DIM,     Wh + 3 * DIM * DIM, Wl + 3 * DIM * DIM);
    tsplit<<<tsG, tsB>>>(Wproj,           DIM,     Wh + 4 * DIM * DIM, Wl + 4 * DIM * DIM);

    const int BIG = 1 << 30;
    dim3 gg(DIM / 128, MROWS / 128);       // (4, 392)
    dim3 gqv(2 * DIM / 128, MROWS / 128);  // (8, 392) fused Q|V

    // K projection (A = x)
    gemm_tc<<<gg,  256, GEMM_SMEM>>>(Xh + 0 * PL, Xl + 0 * PL,
                                     Wh + 0 * DIM * DIM, Wl + 0 * DIM * DIM,
                                     bqkv + DIM, nullptr, K, nullptr, BIG);
    // Q and V projections fused (A = x3; stacked weights, split outputs)
    gemm_tc<<<gqv, 256, GEMM_SMEM>>>(Xh + 2 * PL, Xl + 2 * PL,
                                     Wh + 1 * DIM * DIM, Wl + 1 * DIM * DIM,
                                     bqkv2, bqkv2 + 2 * DIM, Q, V, DIM);
    // Gate (A = x2)
    gemm_tc<<<gg,  256, GEMM_SMEM>>>(Xh + 1 * PL, Xl + 1 * PL,
                                     Wh + 3 * DIM * DIM, Wl + 3 * DIM * DIM,
                                     bgw, nullptr, G, nullptr, BIG);

    attn_kernel<<<NB * NHEAD, 256>>>(Q, G, K, V, a, Oh, Ol);

    // Output projection (A = attention output, already split)
    gemm_tc<<<gg,  256, GEMM_SMEM>>>(Oh, Ol,
                                     Wh + 4 * DIM * DIM, Wl + 4 * DIM * DIM,
                                     bproj, nullptr, out, nullptr, BIG);
}